// round 17
// baseline (speedup 1.0000x reference)
#include <cuda_runtime.h>

#define NQ 12
#define BT 64    // 2 warps; 4 lanes per element slot, 2 elements per lane -> 32/CTA

__device__ __forceinline__ float2 cmulc(float2 a, float2 b) {
    return make_float2(a.x * b.x - a.y * b.y, a.x * b.y + a.y * b.x);
}
__device__ __forceinline__ float2 caddc(float2 a, float2 b) {
    return make_float2(a.x + b.x, a.y + b.y);
}

// Bond-4 MPS transfer-matrix chain, 4 lanes per element (lane owns component
// sg = lane&3, cross-component via shuffles), and TWO elements per lane
// interleaved for ILP (B's shuffles hide A's FMA latency and vice versa).
// Math and K indexing validated through R12/R15/R16.
__global__ __launch_bounds__(BT)
void qnn_mps_kernel(const float* __restrict__ x,
                    const float* __restrict__ params,
                    float* __restrict__ out, int B)
{
    __shared__ float2 sU[3][12][4];   // fused gates [layer][wire][r*2+s]
    __shared__ float2 sK[368];        // bulk [0..351], boundary [352..367]
    __shared__ float  sX[32 * NQ];    // staged x rows (32 elements per CTA)

    const int tid   = threadIdx.x;
    const int lane  = tid & 31;
    const int wid   = tid >> 5;
    const int l     = lane & 3;                // bond component this lane owns
    const int gbase = lane & ~3;               // group leader lane
    const int g     = wid * 8 + (lane >> 2);   // group index 0..15
    const int leA   = g;                       // element A (local 0..15)
    const int leB   = g + 16;                  // element B (local 16..31)
    const int eA    = blockIdx.x * 32 + leA;
    const int eB    = blockIdx.x * 32 + leB;

    // ---- stage x: 32*12 floats = 96 float4, coalesced, guarded -------------
    {
        const float4* x4 = (const float4*)(x) + blockIdx.x * 96;
        int total4 = (B * NQ) / 4 - blockIdx.x * 96;
#pragma unroll
        for (int i = 0; i < 2; ++i) {
            int e4 = i * BT + tid;
            if (e4 < 96)
                ((float4*)sX)[e4] = (e4 < total4) ? x4[e4]
                                                  : make_float4(0.f, 0.f, 0.f, 0.f);
        }
    }

    // ---- fused gates U = RZ RX RY (validated) -------------------------------
    if (tid < 36) {
        const float* p = params + tid * 3;
        float sa, ca; sincosf(0.5f * p[0], &sa, &ca);
        float sb, cb; sincosf(0.5f * p[1], &sb, &cb);
        float sc, cc; sincosf(0.5f * p[2], &sc, &cc);
        float2 m00 = make_float2( cb * ca, -sb * sa);
        float2 m01 = make_float2(-cb * sa, -sb * ca);
        float2 m10 = make_float2( cb * sa, -sb * ca);
        float2 m11 = make_float2( cb * ca,  sb * sa);
        float2 e0 = make_float2(cc, -sc);
        float2 e1 = make_float2(cc,  sc);
        int layer = tid / 12, wire = tid % 12;
        sU[layer][wire][0] = cmulc(e0, m00);
        sU[layer][wire][1] = cmulc(e0, m01);
        sU[layer][wire][2] = cmulc(e1, m10);
        sU[layer][wire][3] = cmulc(e1, m11);
    }
    __syncthreads();

    // ---- K tensors (validated indexing) -------------------------------------
    for (int i = tid; i < 368; i += BT) {
        if (i < 352) {
            int p   = i / 32 + 1;          // 1..11
            int w   = 11 - p;
            int rem = i % 32;
            int s   = rem >> 4;
            int sg  = (rem >> 2) & 3;      // sigma  = a + 2b
            int sgp = rem & 3;             // sigma' = a' + 2b'
            int a = sg & 1,  bq = sg >> 1;
            int ap = sgp & 1, bp = sgp >> 1;
            sK[i] = cmulc(cmulc(sU[2][w][a],
                                sU[1][w][((a ^ ap) << 1) | bq]),
                          sU[0][w][((bq ^ bp) << 1) | s]);
        } else {
            int r   = i - 352;
            int j   = r >> 3;
            int s   = (r >> 2) & 1;
            int sgp = r & 3;
            int ap = sgp & 1, bp = sgp >> 1;
            float2 acc = make_float2(0.0f, 0.0f);
#pragma unroll
            for (int sg = 0; sg < 4; ++sg) {
                int a = sg & 1, bq = sg >> 1;
                acc = caddc(acc,
                    cmulc(cmulc(sU[2][11][(j << 1) | a],
                                sU[1][11][((a ^ ap) << 1) | bq]),
                          sU[0][11][((bq ^ bp) << 1) | s]));
            }
            sK[i] = acc;
        }
    }
    __syncthreads();

    // ---- per-element wire angles --------------------------------------------
    const float* xA = &sX[leA * NQ];
    const float* xB = &sX[leB * NQ];
    float fcA[NQ], fsA[NQ], fcB[NQ], fsB[NQ];
#pragma unroll
    for (int w = 0; w < NQ; ++w) {
        __sincosf(0.5f * xA[w], &fsA[w], &fcA[w]);
        __sincosf(0.5f * xB[w], &fsB[w], &fcB[w]);
    }

    // ---- p = 11 init (wire 0): column 0 of K_11; lane owns sg = l -----------
    float2 wvA, wvB;
    {
        float2 k0 = sK[10 * 32 + l * 4];          // s = 0
        float2 k1 = sK[10 * 32 + 16 + l * 4];     // s = 1
        wvA = make_float2(fcA[0] * k0.x + fsA[0] * k1.x,
                          fcA[0] * k0.y + fsA[0] * k1.y);
        wvB = make_float2(fcB[0] * k0.x + fsB[0] * k1.x,
                          fcB[0] * k0.y + fsB[0] * k1.y);
    }

    // ---- p = 10..1: wv_l <- sum_sp (c*K0 + s*K1)[l][sp] wv_sp, A/B interleaved
#pragma unroll
    for (int p = 10; p >= 1; --p) {
        float cA = fcA[11 - p], sA = fsA[11 - p];
        float cB = fcB[11 - p], sB = fsB[11 - p];
        const float2* kb = &sK[(p - 1) * 32];
        float2 accA = make_float2(0.0f, 0.0f);
        float2 accB = make_float2(0.0f, 0.0f);
#pragma unroll
        for (int sp = 0; sp < 4; ++sp) {
            float wxA = __shfl_sync(0xffffffffu, wvA.x, gbase | sp);
            float wyA = __shfl_sync(0xffffffffu, wvA.y, gbase | sp);
            float wxB = __shfl_sync(0xffffffffu, wvB.x, gbase | sp);
            float wyB = __shfl_sync(0xffffffffu, wvB.y, gbase | sp);
            float2 k0 = kb[l * 4 + sp];
            float2 k1 = kb[16 + l * 4 + sp];
            float2 mA = make_float2(cA * k0.x + sA * k1.x,
                                    cA * k0.y + sA * k1.y);
            float2 mB = make_float2(cB * k0.x + sB * k1.x,
                                    cB * k0.y + sB * k1.y);
            accA = caddc(accA, cmulc(mA, make_float2(wxA, wyA)));
            accB = caddc(accB, cmulc(mB, make_float2(wxB, wyB)));
        }
        wvA = accA;
        wvB = accB;
    }

    // ---- p = 0 boundary: per-lane term + 4-lane butterfly, A/B interleaved --
    float prA[2], prB[2];
#pragma unroll
    for (int j = 0; j < 2; ++j) {
        const float2* ka = &sK[352 + j * 8];
        float2 k0 = ka[l], k1 = ka[4 + l];
        float2 mA = make_float2(fcA[11] * k0.x + fsA[11] * k1.x,
                                fcA[11] * k0.y + fsA[11] * k1.y);
        float2 mB = make_float2(fcB[11] * k0.x + fsB[11] * k1.x,
                                fcB[11] * k0.y + fsB[11] * k1.y);
        float2 tA = cmulc(mA, wvA);
        float2 tB = cmulc(mB, wvB);
        tA.x += __shfl_xor_sync(0xffffffffu, tA.x, 1);
        tA.y += __shfl_xor_sync(0xffffffffu, tA.y, 1);
        tB.x += __shfl_xor_sync(0xffffffffu, tB.x, 1);
        tB.y += __shfl_xor_sync(0xffffffffu, tB.y, 1);
        tA.x += __shfl_xor_sync(0xffffffffu, tA.x, 2);
        tA.y += __shfl_xor_sync(0xffffffffu, tA.y, 2);
        tB.x += __shfl_xor_sync(0xffffffffu, tB.x, 2);
        tB.y += __shfl_xor_sync(0xffffffffu, tB.y, 2);
        prA[j] = tA.x * tA.x + tA.y * tA.y;
        prB[j] = tB.x * tB.x + tB.y * tB.y;
    }

    if (l == 0) {
        if (eA < B) {
            float inv = 1.0f / (prA[0] + prA[1]);
            ((float2*)out)[eA] = make_float2(prA[0] * inv, prA[1] * inv);
        }
        if (eB < B) {
            float inv = 1.0f / (prB[0] + prB[1]);
            ((float2*)out)[eB] = make_float2(prB[0] * inv, prB[1] * inv);
        }
    }
}

extern "C" void kernel_launch(void* const* d_in, const int* in_sizes, int n_in,
                              void* d_out, int out_size) {
    const float* x      = (const float*)d_in[0];  // (B, 12) float32
    const float* params = (const float*)d_in[1];  // (3, 12, 3) float32
    float* out = (float*)d_out;                   // (B, 2) float32
    int B = in_sizes[0] / NQ;

    qnn_mps_kernel<<<(B + 31) / 32, BT>>>(x, params, out, B);
}